// round 3
// baseline (speedup 1.0000x reference)
#include <cuda_runtime.h>
#include <math.h>

#define BATCH    2048
#define FID      65536
#define CHUNK    1024              // columns per block (256 threads * float4)
#define NCHUNK   (FID / CHUNK)     // 64
#define ROWS_PB  16                // rows per block
#define NROWG    (BATCH / ROWS_PB) // 128
#define WARPS_PB 8                 // 256 threads

// Scratch (device globals are zero-initialized; counters self-reset each run)
__device__ float        g_partials[BATCH * NCHUNK];   // 512 KB
__device__ float        g_lossp[NROWG];
__device__ unsigned int g_rg_count[NROWG];
__device__ unsigned int g_final_count;

// ---------------------------------------------------------------------------
// Fully fused kernel: dot partials + per-row-group finalize (last of 64
// chunk-blocks) + global loss reduce (last of 128 finalizer blocks).
// out layout: [logits(2048), pred(2048), loss(1)]
// ---------------------------------------------------------------------------
__global__ void __launch_bounds__(256) lr_fused_kernel(
    const float* __restrict__ gate, const float* __restrict__ bias,
    const float* __restrict__ global_bias, const float* __restrict__ label,
    float* __restrict__ out)
{
    const int c    = blockIdx.x;        // column chunk 0..63
    const int g    = blockIdx.y;        // row group 0..127
    const int tid  = threadIdx.x;       // 0..255
    const int warp = tid >> 5;
    const int lane = tid & 31;

    // ---------------- Phase A: masked dot over this (rowgroup, chunk) tile ----
    const int col = c * CHUNK + tid * 4;
    const float4 b4 = *reinterpret_cast<const float4*>(bias + col);
    const float* gbase = gate + (size_t)(g * ROWS_PB) * FID + col;

    __shared__ float sm[ROWS_PB][WARPS_PB];

#pragma unroll
    for (int r = 0; r < ROWS_PB; ++r) {
        float4 x = __ldcs(reinterpret_cast<const float4*>(gbase + (size_t)r * FID));
        float v = x.x * b4.x + x.y * b4.y + x.z * b4.z + x.w * b4.w;
        v += __shfl_xor_sync(0xffffffffu, v, 16);
        v += __shfl_xor_sync(0xffffffffu, v, 8);
        v += __shfl_xor_sync(0xffffffffu, v, 4);
        v += __shfl_xor_sync(0xffffffffu, v, 2);
        v += __shfl_xor_sync(0xffffffffu, v, 1);
        if (lane == 0) sm[r][warp] = v;
    }
    __syncthreads();

    if (tid < ROWS_PB) {
        float t = 0.0f;
#pragma unroll
        for (int w = 0; w < WARPS_PB; ++w) t += sm[tid][w];
        g_partials[(size_t)(g * ROWS_PB + tid) * NCHUNK + c] = t;
    }
    __syncthreads();

    // ---------------- Phase B: last chunk-block of this row group finalizes ---
    __shared__ int s_is_final;
    if (tid == 0) {
        __threadfence();
        unsigned old = atomicAdd(&g_rg_count[g], 1u);
        s_is_final = (old == NCHUNK - 1);
        if (s_is_final) g_rg_count[g] = 0;   // reset for next graph replay
    }
    __syncthreads();
    if (!s_is_final) return;
    __threadfence();  // acquire: make other blocks' partials visible

    // 8 warps, 2 rows per warp; 64 partials per row (lane reads 2)
    __shared__ float sloss[ROWS_PB];
#pragma unroll
    for (int rr = 0; rr < 2; ++rr) {
        const int row = g * ROWS_PB + warp * 2 + rr;
        const float* p = g_partials + (size_t)row * NCHUNK;
        float s = p[lane] + p[lane + 32];
        s += __shfl_xor_sync(0xffffffffu, s, 16);
        s += __shfl_xor_sync(0xffffffffu, s, 8);
        s += __shfl_xor_sync(0xffffffffu, s, 4);
        s += __shfl_xor_sync(0xffffffffu, s, 2);
        s += __shfl_xor_sync(0xffffffffu, s, 1);
        if (lane == 0) {
            float logit = s + global_bias[0];
            out[row]         = logit;
            out[BATCH + row] = 1.0f / (1.0f + __expf(-logit));
            float y = label[row];
            sloss[warp * 2 + rr] =
                fmaxf(logit, 0.0f) - logit * y + log1pf(expf(-fabsf(logit)));
        }
    }
    __syncthreads();

    // ---------------- Phase C: per-group loss, then global reduce -------------
    __shared__ int s_is_last;
    if (tid == 0) {
        float gl = 0.0f;
#pragma unroll
        for (int r = 0; r < ROWS_PB; ++r) gl += sloss[r];  // fixed order
        g_lossp[g] = gl;
        __threadfence();
        unsigned old = atomicAdd(&g_final_count, 1u);
        s_is_last = (old == NROWG - 1);
        if (s_is_last) g_final_count = 0;    // reset for next graph replay
    }
    __syncthreads();
    if (!s_is_last) return;

    if (tid == 0) {
        __threadfence();
        float total = 0.0f;
        for (int i = 0; i < NROWG; ++i) total += g_lossp[i];  // fixed order
        out[2 * BATCH] = total;
    }
}

// ---------------------------------------------------------------------------
extern "C" void kernel_launch(void* const* d_in, const int* in_sizes, int n_in,
                              void* d_out, int out_size)
{
    const float* gate        = (const float*)d_in[0]; // [2048, 65536]
    const float* sparse_bias = (const float*)d_in[1]; // [65536]
    const float* global_bias = (const float*)d_in[2]; // [1]
    const float* label       = (const float*)d_in[3]; // [2048]
    float* out = (float*)d_out;                       // [4097]

    dim3 grid(NCHUNK, NROWG);
    lr_fused_kernel<<<grid, 256>>>(gate, sparse_bias, global_bias, label, out);
}

// round 4
// speedup vs baseline: 1.0019x; 1.0019x over previous
#include <cuda_runtime.h>
#include <math.h>

#define BATCH    2048
#define FID      65536
#define CHUNK    1024              // columns per block (256 threads * float4)
#define NCHUNK   (FID / CHUNK)     // 64
#define ROWS_PB  16                // rows per inner tile
#define NROWG    (BATCH / ROWS_PB) // 128 row groups
#define GY_SLOTS 16                // rowgroup slots in grid (single wave)
#define G_ITERS  (NROWG / GY_SLOTS) // 8 rowgroups per block
#define WARPS_PB 8                 // 256 threads

// Scratch (device globals zero-initialized; counter self-resets each run)
__device__ float        g_partials[BATCH * NCHUNK];   // 512 KB
__device__ float        g_lossp[64];
__device__ unsigned int g_final_count;

// ---------------------------------------------------------------------------
// Kernel 1: single-wave streaming kernel. Grid (64, 16) = 1024 blocks fits in
// one wave (148 SMs x 8 blocks). Each block holds its bias chunk in registers
// and loops over 8 row groups (128 rows total) -> no wave transitions, bias
// loaded once per block.
// ---------------------------------------------------------------------------
__global__ void __launch_bounds__(256) dot_partials_kernel(
    const float* __restrict__ gate, const float* __restrict__ bias)
{
    const int c    = blockIdx.x;        // column chunk 0..63
    const int gy   = blockIdx.y;        // rowgroup slot 0..15
    const int tid  = threadIdx.x;
    const int warp = tid >> 5;
    const int lane = tid & 31;

    const int col = c * CHUNK + tid * 4;
    const float4 b4 = *reinterpret_cast<const float4*>(bias + col);

    __shared__ float sm[ROWS_PB][WARPS_PB];

    for (int gi = 0; gi < G_ITERS; ++gi) {
        const int g = gy + gi * GY_SLOTS;   // 0..127
        const float* gbase = gate + (size_t)(g * ROWS_PB) * FID + col;

#pragma unroll
        for (int r = 0; r < ROWS_PB; ++r) {
            float4 x = *reinterpret_cast<const float4*>(gbase + (size_t)r * FID);
            float v = x.x * b4.x + x.y * b4.y + x.z * b4.z + x.w * b4.w;
            v += __shfl_xor_sync(0xffffffffu, v, 16);
            v += __shfl_xor_sync(0xffffffffu, v, 8);
            v += __shfl_xor_sync(0xffffffffu, v, 4);
            v += __shfl_xor_sync(0xffffffffu, v, 2);
            v += __shfl_xor_sync(0xffffffffu, v, 1);
            if (lane == 0) sm[r][warp] = v;
        }
        __syncthreads();

        if (tid < ROWS_PB) {
            float t = 0.0f;
#pragma unroll
            for (int w = 0; w < WARPS_PB; ++w) t += sm[tid][w];
            g_partials[(size_t)(g * ROWS_PB + tid) * NCHUNK + c] = t;
        }
        __syncthreads();
    }
}

// ---------------------------------------------------------------------------
// Kernel 2: merged epilogue. 64 blocks x 256 threads; each warp finalizes
// 4 rows (logits, pred, per-example loss). Block loss partial -> g_lossp;
// last block reduces the 64 partials (deterministic shfl tree).
// out layout: [logits(2048), pred(2048), loss(1)]
// ---------------------------------------------------------------------------
__global__ void __launch_bounds__(256) finalize_kernel(
    const float* __restrict__ label, const float* __restrict__ global_bias,
    float* __restrict__ out)
{
    const int warp = threadIdx.x >> 5;
    const int lane = threadIdx.x & 31;
    const int tid  = threadIdx.x;

    __shared__ float sloss[32];   // 8 warps * 4 rows
    const float gb = global_bias[0];

#pragma unroll
    for (int rr = 0; rr < 4; ++rr) {
        const int row = blockIdx.x * 32 + warp * 4 + rr;
        const float* p = g_partials + (size_t)row * NCHUNK;
        float s = p[lane] + p[lane + 32];
        s += __shfl_xor_sync(0xffffffffu, s, 16);
        s += __shfl_xor_sync(0xffffffffu, s, 8);
        s += __shfl_xor_sync(0xffffffffu, s, 4);
        s += __shfl_xor_sync(0xffffffffu, s, 2);
        s += __shfl_xor_sync(0xffffffffu, s, 1);
        if (lane == 0) {
            float logit = s + gb;
            out[row]         = logit;
            out[BATCH + row] = 1.0f / (1.0f + __expf(-logit));
            float y = label[row];
            sloss[warp * 4 + rr] =
                fmaxf(logit, 0.0f) - logit * y + log1pf(expf(-fabsf(logit)));
        }
    }
    __syncthreads();

    // warp 0 reduces this block's 32 per-row losses
    if (warp == 0) {
        float v = sloss[lane];
        v += __shfl_xor_sync(0xffffffffu, v, 16);
        v += __shfl_xor_sync(0xffffffffu, v, 8);
        v += __shfl_xor_sync(0xffffffffu, v, 4);
        v += __shfl_xor_sync(0xffffffffu, v, 2);
        v += __shfl_xor_sync(0xffffffffu, v, 1);
        if (lane == 0) g_lossp[blockIdx.x] = v;
    }

    // last block sums the 64 block partials
    __shared__ int s_is_last;
    if (tid == 0) {
        __threadfence();
        unsigned old = atomicAdd(&g_final_count, 1u);
        s_is_last = (old == 63);
        if (s_is_last) g_final_count = 0;  // reset for next graph replay
    }
    __syncthreads();
    if (!s_is_last) return;

    if (warp == 0) {
        __threadfence();
        float v = g_lossp[lane] + g_lossp[lane + 32];
        v += __shfl_xor_sync(0xffffffffu, v, 16);
        v += __shfl_xor_sync(0xffffffffu, v, 8);
        v += __shfl_xor_sync(0xffffffffu, v, 4);
        v += __shfl_xor_sync(0xffffffffu, v, 2);
        v += __shfl_xor_sync(0xffffffffu, v, 1);
        if (lane == 0) out[2 * BATCH] = v;
    }
}

// ---------------------------------------------------------------------------
extern "C" void kernel_launch(void* const* d_in, const int* in_sizes, int n_in,
                              void* d_out, int out_size)
{
    const float* gate        = (const float*)d_in[0]; // [2048, 65536]
    const float* sparse_bias = (const float*)d_in[1]; // [65536]
    const float* global_bias = (const float*)d_in[2]; // [1]
    const float* label       = (const float*)d_in[3]; // [2048]
    float* out = (float*)d_out;                       // [4097]

    dim3 grid1(NCHUNK, GY_SLOTS);
    dot_partials_kernel<<<grid1, 256>>>(gate, sparse_bias);
    finalize_kernel<<<64, 256>>>(label, global_bias, out);
}